// round 6
// baseline (speedup 1.0000x reference)
#include <cuda_runtime.h>
#include <cuda_bf16.h>
#include <cstdint>

#define XDIM 512
#define YDIM 512
#define NPIX (XDIM*YDIM)      // 262144
#define VNUM 150000
#define HID 64
#define CO 256
#define KEFF 6912             // 9 taps * 256 ch * 3 slots
#define KROW 768              // per-pixel slots (256 ch * 3 slots)

// ---------------- scratch ----------------
__device__ __align__(256) float g_bev0[NPIX*HID];
__device__ __align__(256) float g_buf1[(size_t)NPIX*CO];
__device__ __align__(256) float g_buf2[(size_t)NPIX*CO];
__device__ __align__(256) __nv_bfloat16 g_a3a[(size_t)NPIX*KROW];
__device__ __align__(256) __nv_bfloat16 g_a3b[(size_t)NPIX*KROW];
__device__ __align__(256) float g_wt1[HID*CO];
__device__ __align__(256) __nv_bfloat16 g_b3A[(size_t)CO*KEFF];
__device__ __align__(256) __nv_bfloat16 g_b3B[(size_t)CO*KEFF];
__device__ __align__(256) float g_stats[4*CO];
__device__ __align__(256) float g_bn[4*CO];

__device__ __forceinline__ uint32_t smem_u32(const void* p) {
    uint32_t a;
    asm("{ .reg .u64 t; cvta.to.shared.u64 t, %1; cvt.u32.u64 %0, t; }" : "=r"(a) : "l"(p));
    return a;
}
__device__ __forceinline__ void split_bf16(float x, __nv_bfloat16& hi, __nv_bfloat16& lo) {
    hi = __float2bfloat16_rn(x);
    lo = __float2bfloat16_rn(x - __bfloat162float(hi));
}

#define LDSM_X4(r0,r1,r2,r3,addr) \
    asm volatile("ldmatrix.sync.aligned.m8n8.x4.shared.b16 {%0,%1,%2,%3}, [%4];" \
        : "=r"(r0),"=r"(r1),"=r"(r2),"=r"(r3) : "r"(addr))
#define MMA_BF16(d, a, b) \
    asm volatile("mma.sync.aligned.m16n8k16.row.col.f32.bf16.bf16.f32 " \
        "{%0,%1,%2,%3},{%4,%5,%6,%7},{%8,%9},{%0,%1,%2,%3};" \
        : "+f"((d)[0]),"+f"((d)[1]),"+f"((d)[2]),"+f"((d)[3]) \
        : "r"((a)[0]),"r"((a)[1]),"r"((a)[2]),"r"((a)[3]),"r"((b)[0]),"r"((b)[1]))
#define CP_ASYNC(dst, src, sz) \
    asm volatile("cp.async.cg.shared.global [%0], [%1], 16, %2;" \
        :: "r"(dst), "l"(src), "r"(sz))
#define CP_COMMIT() asm volatile("cp.async.commit_group;")
#define CP_WAIT1()  asm volatile("cp.async.wait_group 1;")
#define CP_WAIT0()  asm volatile("cp.async.wait_group 0;")

// ---------------- zero bev + stats ----------------
__global__ void zero_kernel() {
    float4* p = (float4*)g_bev0;
    const int n4 = NPIX*HID/4;
    for (int i = blockIdx.x*blockDim.x + threadIdx.x; i < n4; i += gridDim.x*blockDim.x)
        p[i] = make_float4(0.f,0.f,0.f,0.f);
    if (blockIdx.x == 0)
        for (int i = threadIdx.x; i < 4*CO; i += blockDim.x) g_stats[i] = 0.f;
}

// ---------------- weight prep ----------------
__global__ void prep_weights(const float* __restrict__ c1w,
                             const float* __restrict__ cAw,
                             const float* __restrict__ cBw) {
    const int total1 = HID*CO;
    const int totalc = CO*CO*9;
    for (int i = blockIdx.x*blockDim.x + threadIdx.x; i < total1 + 2*totalc;
         i += gridDim.x*blockDim.x) {
        if (i < total1) {
            int o = i & 255, c = i >> 8;
            g_wt1[i] = c1w[o*HID + c];
        } else {
            int j = i - total1;
            const float* src = cAw; __nv_bfloat16* dst = g_b3A;
            if (j >= totalc) { j -= totalc; src = cBw; dst = g_b3B; }
            int o = j / 2304, k = j % 2304;
            int c = k / 9, tap = k % 9;
            float w = src[(size_t)o*2304 + c*9 + tap];
            __nv_bfloat16 hi, lo; split_bf16(w, hi, lo);
            size_t base = (size_t)o*KEFF + tap*KROW;
            dst[base + c]       = hi;
            dst[base + 256 + c] = lo;
            dst[base + 512 + c] = hi;
        }
    }
}

// ---------------- pillar MLP + pool + scatter ----------------
__global__ void __launch_bounds__(128) pillar_mlp(
    const float* __restrict__ pillars, const int* __restrict__ nump,
    const int* __restrict__ indices, const float* __restrict__ w1,
    const float* __restrict__ b1, const float* __restrict__ w2,
    const float* __restrict__ b2)
{
    __shared__ __align__(16) float w2q[64*64];
    __shared__ __align__(16) float h1s[2][32*64];
    __shared__ __align__(16) float pts[2][128];
    const int tid = threadIdx.x;
    const int g = tid >> 6, t = tid & 63;
    const int v = blockIdx.x*2 + g;

    for (int i = tid; i < 4096; i += 128) {
        int tt = i >> 6, j = i & 63;
        w2q[((j>>2)*64 + tt)*4 + (j&3)] = w2[i];
    }
    float4 w1r = *(const float4*)(w1 + t*4);
    float b1t = b1[t], b2t = b2[t];

    bool valid = false; int xy = 0;
    if (v < VNUM) {
        float mask = (nump[v] > 0) ? 1.f : 0.f;
        int xs = indices[2*v], ys = indices[2*v+1];
        if ((unsigned)xs < XDIM && (unsigned)ys < YDIM) { valid = true; xy = xs*YDIM + ys; }
        pts[g][t]      = pillars[(size_t)v*128 + t] * mask;
        pts[g][t + 64] = pillars[(size_t)v*128 + 64 + t] * mask;
    } else { pts[g][t] = 0.f; pts[g][t + 64] = 0.f; }
    __syncthreads();

    #pragma unroll
    for (int p = 0; p < 32; p++) {
        float4 xp = *(float4*)&pts[g][p*4];
        float h = fmaf(w1r.x, xp.x, fmaf(w1r.y, xp.y, fmaf(w1r.z, xp.z, fmaf(w1r.w, xp.w, b1t))));
        h1s[g][p*64 + t] = fmaxf(h, 0.f);
    }
    __syncthreads();

    float acc = 0.f;
    #pragma unroll
    for (int po = 0; po < 4; po++) {
        float s[8];
        #pragma unroll
        for (int pp = 0; pp < 8; pp++) s[pp] = b2t;
        #pragma unroll
        for (int jq = 0; jq < 16; jq++) {
            float4 w = *(float4*)&w2q[(jq*64 + t)*4];
            #pragma unroll
            for (int pp = 0; pp < 8; pp++) {
                float4 hh = *(float4*)&h1s[g][(po*8 + pp)*64 + jq*4];
                s[pp] = fmaf(w.x, hh.x, s[pp]); s[pp] = fmaf(w.y, hh.y, s[pp]);
                s[pp] = fmaf(w.z, hh.z, s[pp]); s[pp] = fmaf(w.w, hh.w, s[pp]);
            }
        }
        #pragma unroll
        for (int pp = 0; pp < 8; pp++) acc += fmaxf(s[pp], 0.f);
    }
    if (valid) g_bev0[(size_t)xy*HID + t] = acc * (1.f/32.f);
}

// ---------------- conv1 (1x1, 64->256) fp32 SIMT, emits 3-slot bf16 A3 --------
__global__ void __launch_bounds__(256) conv1_gemm(
    const float* __restrict__ in, const float* __restrict__ wt,
    const float* __restrict__ bias, __nv_bfloat16* __restrict__ a3)
{
    __shared__ __align__(16) float As[16*68];
    __shared__ __align__(16) float Bs[16*64];
    const int tid = threadIdx.x;
    const int tx = tid & 15, ty = tid >> 4;
    const int pix0 = blockIdx.x * 64;
    const int o0 = blockIdx.y * 64;

    const int ai = tid >> 2;
    const int ak = (tid & 3) * 4;
    const int bj = tid & 63;
    const int bk0 = tid >> 6;

    float acc[4][4] = {};
    float4 av; float bv[4];
    #pragma unroll
    for (int k0 = 0; k0 < 64; k0 += 16) {
        av = *(const float4*)(in + (size_t)(pix0 + ai)*HID + k0 + ak);
        #pragma unroll
        for (int m = 0; m < 4; m++) bv[m] = wt[(size_t)(k0 + bk0 + m*4)*CO + o0 + bj];
        As[(ak+0)*68 + ai] = av.x; As[(ak+1)*68 + ai] = av.y;
        As[(ak+2)*68 + ai] = av.z; As[(ak+3)*68 + ai] = av.w;
        #pragma unroll
        for (int m = 0; m < 4; m++) Bs[(bk0 + m*4)*64 + bj] = bv[m];
        __syncthreads();
        #pragma unroll
        for (int kk = 0; kk < 16; kk++) {
            float4 a4 = *(float4*)&As[kk*68 + ty*4];
            float4 b4 = *(float4*)&Bs[kk*64 + tx*4];
            float aa[4] = {a4.x,a4.y,a4.z,a4.w}, bb[4] = {b4.x,b4.y,b4.z,b4.w};
            #pragma unroll
            for (int r = 0; r < 4; r++)
                #pragma unroll
                for (int c = 0; c < 4; c++) acc[r][c] = fmaf(aa[r], bb[c], acc[r][c]);
        }
        __syncthreads();
    }
    float4 bvz = *(const float4*)(bias + o0 + tx*4);
    float bbias[4] = {bvz.x,bvz.y,bvz.z,bvz.w};
    #pragma unroll
    for (int r = 0; r < 4; r++) {
        int pix = pix0 + ty*4 + r;
        __nv_bfloat16 hi[4], lo[4];
        #pragma unroll
        for (int c = 0; c < 4; c++) split_bf16(acc[r][c] + bbias[c], hi[c], lo[c]);
        __nv_bfloat16* dst = a3 + (size_t)pix*KROW + o0 + tx*4;
        uint2 h2 = make_uint2(
            ((uint32_t)__bfloat16_as_ushort(hi[0])) | ((uint32_t)__bfloat16_as_ushort(hi[1]) << 16),
            ((uint32_t)__bfloat16_as_ushort(hi[2])) | ((uint32_t)__bfloat16_as_ushort(hi[3]) << 16));
        uint2 l2 = make_uint2(
            ((uint32_t)__bfloat16_as_ushort(lo[0])) | ((uint32_t)__bfloat16_as_ushort(lo[1]) << 16),
            ((uint32_t)__bfloat16_as_ushort(lo[2])) | ((uint32_t)__bfloat16_as_ushort(lo[3]) << 16));
        *(uint2*)(dst)       = h2;
        *(uint2*)(dst + 256) = h2;
        *(uint2*)(dst + 512) = l2;
    }
}

// ---------------- mma.sync 3x3 conv: 128 pix x 256 oc tile, K=6912 ----------
// 8 warps (2M x 4N), warp tile 64x64, chunks of 64 K-slots, cp.async dbl-buffer
// smem: A dbl [0,32K), B dbl [32K,96K), bias [96K,97K)
__global__ void __launch_bounds__(256, 1) conv_mma(
    const __nv_bfloat16* __restrict__ a3w, const __nv_bfloat16* __restrict__ b3w,
    const float* __restrict__ bias, float* __restrict__ out,
    float* __restrict__ sumb, float* __restrict__ sqb)
{
    extern __shared__ char sm[];
    const char* a3 = (const char*)a3w;
    const char* b3 = (const char*)b3w;
    const int tid = threadIdx.x, wid = tid >> 5, lane = tid & 31;
    const int wm = wid >> 2, wn = wid & 3;
    const uint32_t sb = smem_u32(sm);
    float* sbias = (float*)(sm + 98304);

    const int xr = blockIdx.x >> 2;               // x-row 0..511
    const int y0 = (blockIdx.x & 3) * 128;        // y base
    const int p0 = xr*512 + y0;

    sbias[tid] = bias[tid];

    // per-lane ldmatrix offsets (no-trans; rows = m for A, n for B; k along row)
    const int a_row = wm*64 + (lane & 15);
    const int a_kb  = (lane >> 4) * 16;
    const int b_row = wn*64 + ((lane & 16) >> 1) + (lane & 7);
    const int b_kb  = (lane & 8) ? 16 : 0;

    // cp.async thread mapping
    const int l_row = tid >> 3;        // 0..31, +32 per i
    const int l_j   = (tid & 7) * 16;  // byte col

    float acc[4][8][4];
    #pragma unroll
    for (int i = 0; i < 4; i++)
        #pragma unroll
        for (int j = 0; j < 8; j++)
            #pragma unroll
            for (int k = 0; k < 4; k++) acc[i][j][k] = 0.f;

    auto load_chunk = [&](int c, int buf) {
        const int tap = c / 12, kc = c - tap*12;
        const int dx = tap/3 - 1, dyy = tap - (tap/3)*3 - 1;
        const int xx = xr + dx;
        const bool xok = (unsigned)xx < XDIM;
        const uint32_t abase = sb + buf*16384u;
        const uint32_t bbase = sb + 32768u + buf*32768u;
        #pragma unroll
        for (int i = 0; i < 4; i++) {
            int row = l_row + i*32;
            int yy = y0 + row + dyy;
            bool ok = xok && ((unsigned)yy < YDIM);
            const char* src = ok ? (a3 + ((size_t)(xx*512 + yy))*1536 + kc*128 + l_j)
                                 : a3;
            uint32_t off = row*128 + l_j; off ^= (off >> 3) & 0x70;
            CP_ASYNC(abase + off, src, ok ? 16 : 0);
        }
        #pragma unroll
        for (int i = 0; i < 8; i++) {
            int row = l_row + i*32;
            const char* src = b3 + (size_t)row*13824 + tap*1536 + kc*128 + l_j;
            uint32_t off = row*128 + l_j; off ^= (off >> 3) & 0x70;
            CP_ASYNC(bbase + off, src, 16);
        }
    };

    load_chunk(0, 0);
    CP_COMMIT();

    for (int c = 0; c < 108; c++) {
        const int buf = c & 1;
        if (c + 1 < 108) { load_chunk(c + 1, buf ^ 1); CP_COMMIT(); CP_WAIT1(); }
        else             { CP_WAIT0(); }
        __syncthreads();

        const uint32_t sa  = sb + buf*16384u;
        const uint32_t sbm = sb + 32768u + buf*32768u;
        #pragma unroll
        for (int ks = 0; ks < 4; ks++) {
            uint32_t af[4][4], bf[8][2];
            #pragma unroll
            for (int mt = 0; mt < 4; mt++) {
                uint32_t off = (a_row + mt*16)*128 + a_kb + ks*32;
                off ^= (off >> 3) & 0x70;
                LDSM_X4(af[mt][0], af[mt][1], af[mt][2], af[mt][3], sa + off);
            }
            #pragma unroll
            for (int pr = 0; pr < 4; pr++) {
                uint32_t off = (b_row + pr*16)*128 + b_kb + ks*32;
                off ^= (off >> 3) & 0x70;
                LDSM_X4(bf[pr*2][0], bf[pr*2][1], bf[pr*2+1][0], bf[pr*2+1][1], sbm + off);
            }
            #pragma unroll
            for (int mt = 0; mt < 4; mt++)
                #pragma unroll
                for (int nt = 0; nt < 8; nt++)
                    MMA_BF16(acc[mt][nt], af[mt], bf[nt]);
        }
        __syncthreads();
    }

    // epilogue: bias add, HWC store, BN stats
    #pragma unroll
    for (int nt = 0; nt < 8; nt++) {
        const int col = wn*64 + nt*8 + (lane & 3)*2;
        const float bs0 = sbias[col];
        const float bs1 = sbias[col + 1];
        float s0 = 0.f, q0 = 0.f, s1 = 0.f, q1 = 0.f;
        #pragma unroll
        for (int mt = 0; mt < 4; mt++) {
            const int prow = p0 + wm*64 + mt*16 + (lane >> 2);
            float v00 = acc[mt][nt][0] + bs0;
            float v01 = acc[mt][nt][1] + bs1;
            float v10 = acc[mt][nt][2] + bs0;
            float v11 = acc[mt][nt][3] + bs1;
            *(float2*)(out + (size_t)prow*CO + col)     = make_float2(v00, v01);
            *(float2*)(out + (size_t)(prow+8)*CO + col) = make_float2(v10, v11);
            s0 += v00 + v10; q0 += v00*v00 + v10*v10;
            s1 += v01 + v11; q1 += v01*v01 + v11*v11;
        }
        #pragma unroll
        for (int o = 4; o < 32; o <<= 1) {
            s0 += __shfl_xor_sync(0xffffffffu, s0, o);
            q0 += __shfl_xor_sync(0xffffffffu, q0, o);
            s1 += __shfl_xor_sync(0xffffffffu, s1, o);
            q1 += __shfl_xor_sync(0xffffffffu, q1, o);
        }
        if (lane < 4) {
            atomicAdd(sumb + col, s0); atomicAdd(sqb + col, q0);
            atomicAdd(sumb + col + 1, s1); atomicAdd(sqb + col + 1, q1);
        }
    }
}

// ---------------- BN finalize ----------------
__global__ void bn_finalize(const float* __restrict__ gamma,
                            const float* __restrict__ beta, int which) {
    int c = threadIdx.x;
    const float inv_n = 1.f / (float)NPIX;
    float mean = g_stats[which*512 + c] * inv_n;
    float var  = g_stats[which*512 + 256 + c] * inv_n - mean*mean;
    float sc = gamma[c] * rsqrtf(var + 1e-5f);
    g_bn[which*512 + c] = sc;
    g_bn[which*512 + 256 + c] = fmaf(-mean, sc, beta[c]);
}

// ---------------- BN-A apply + relu + 3-slot bf16 convert ----------------
__global__ void bn_convert(const float* __restrict__ in, __nv_bfloat16* __restrict__ a3) {
    __shared__ float sc[256], sh[256];
    if (threadIdx.x < 256) {
        sc[threadIdx.x] = g_bn[threadIdx.x];
        sh[threadIdx.x] = g_bn[256 + threadIdx.x];
    }
    __syncthreads();
    const float4* in4 = (const float4*)in;
    const int total4 = NPIX * 64;
    for (int i = blockIdx.x*blockDim.x + threadIdx.x; i < total4; i += gridDim.x*blockDim.x) {
        float4 v = in4[i];
        int c = (i & 63) * 4;
        size_t pix = (size_t)(i >> 6);
        float f[4] = {v.x, v.y, v.z, v.w};
        __nv_bfloat16 hi[4], lo[4];
        #pragma unroll
        for (int cc = 0; cc < 4; cc++) {
            float y = fmaxf(fmaf(f[cc], sc[c+cc], sh[c+cc]), 0.f);
            split_bf16(y, hi[cc], lo[cc]);
        }
        __nv_bfloat16* dst = a3 + pix*KROW + c;
        uint2 h2 = make_uint2(
            ((uint32_t)__bfloat16_as_ushort(hi[0])) | ((uint32_t)__bfloat16_as_ushort(hi[1]) << 16),
            ((uint32_t)__bfloat16_as_ushort(hi[2])) | ((uint32_t)__bfloat16_as_ushort(hi[3]) << 16));
        uint2 l2 = make_uint2(
            ((uint32_t)__bfloat16_as_ushort(lo[0])) | ((uint32_t)__bfloat16_as_ushort(lo[1]) << 16),
            ((uint32_t)__bfloat16_as_ushort(lo[2])) | ((uint32_t)__bfloat16_as_ushort(lo[3]) << 16));
        *(uint2*)(dst)       = h2;
        *(uint2*)(dst + 256) = h2;
        *(uint2*)(dst + 512) = l2;
    }
}

// ---------------- BN-B apply + relu + HWC->NCHW ----------------
__global__ void __launch_bounds__(256) bn_apply_nchw(const float* __restrict__ in,
                                                     float* __restrict__ out) {
    __shared__ float s[32*257];
    const int tid = threadIdx.x;
    const float sc = g_bn[512 + tid];
    const float sh = g_bn[768 + tid];
    const int xy0 = blockIdx.x * 32;
    #pragma unroll
    for (int m = 0; m < 32; m++) {
        float v = in[(size_t)(xy0 + m)*CO + tid];
        s[m*257 + tid] = fmaxf(fmaf(v, sc, sh), 0.f);
    }
    __syncthreads();
    #pragma unroll
    for (int m = 0; m < 32; m++) {
        int o = m*8 + (tid >> 5);
        int xyl = tid & 31;
        out[(size_t)o*NPIX + xy0 + xyl] = s[xyl*257 + o];
    }
}

// ---------------- launch ----------------
extern "C" void kernel_launch(void* const* d_in, const int* in_sizes, int n_in,
                              void* d_out, int out_size) {
    const float* pillars = (const float*)d_in[0];
    const int*   nump    = (const int*)d_in[1];
    const int*   indices = (const int*)d_in[2];
    const float* w1   = (const float*)d_in[3];
    const float* b1   = (const float*)d_in[4];
    const float* w2   = (const float*)d_in[5];
    const float* b2   = (const float*)d_in[6];
    const float* c1w  = (const float*)d_in[7];
    const float* c1b  = (const float*)d_in[8];
    const float* cAw  = (const float*)d_in[9];
    const float* cAb  = (const float*)d_in[10];
    const float* bnAg = (const float*)d_in[11];
    const float* bnAb = (const float*)d_in[12];
    const float* cBw  = (const float*)d_in[13];
    const float* cBb  = (const float*)d_in[14];
    const float* bnBg = (const float*)d_in[15];
    const float* bnBb = (const float*)d_in[16];
    float* out = (float*)d_out;

    float *p_bev0, *p_buf1, *p_buf2, *p_wt1, *p_stats;
    __nv_bfloat16 *p_a3a, *p_a3b, *p_b3A, *p_b3B;
    cudaGetSymbolAddress((void**)&p_bev0,  g_bev0);
    cudaGetSymbolAddress((void**)&p_buf1,  g_buf1);
    cudaGetSymbolAddress((void**)&p_buf2,  g_buf2);
    cudaGetSymbolAddress((void**)&p_wt1,   g_wt1);
    cudaGetSymbolAddress((void**)&p_stats, g_stats);
    cudaGetSymbolAddress((void**)&p_a3a,   g_a3a);
    cudaGetSymbolAddress((void**)&p_a3b,   g_a3b);
    cudaGetSymbolAddress((void**)&p_b3A,   g_b3A);
    cudaGetSymbolAddress((void**)&p_b3B,   g_b3B);

    static bool attr_done = false;
    if (!attr_done) {
        cudaFuncSetAttribute(conv_mma, cudaFuncAttributeMaxDynamicSharedMemorySize, 99328);
        attr_done = true;
    }

    zero_kernel<<<2048, 256>>>();
    prep_weights<<<1200, 256>>>(c1w, cAw, cBw);
    pillar_mlp<<<(VNUM + 1)/2, 128>>>(pillars, nump, indices, w1, b1, w2, b2);

    dim3 c1grid(NPIX/64, 4);
    conv1_gemm<<<c1grid, 256>>>(p_bev0, p_wt1, c1b, p_a3a);

    conv_mma<<<2048, 256, 99328>>>(p_a3a, p_b3A, cAb, p_buf1, p_stats, p_stats + 256);
    bn_finalize<<<1, 256>>>(bnAg, bnAb, 0);

    bn_convert<<<4096, 256>>>(p_buf1, p_a3b);

    conv_mma<<<2048, 256, 99328>>>(p_a3b, p_b3B, cBb, p_buf2, p_stats + 512, p_stats + 768);
    bn_finalize<<<1, 256>>>(bnBg, bnBb, 1);

    bn_apply_nchw<<<NPIX/32, 256>>>(p_buf2, out);
}

// round 7
// speedup vs baseline: 2.0078x; 2.0078x over previous
#include <cuda_runtime.h>
#include <cuda_bf16.h>
#include <cuda_fp16.h>
#include <cstdint>

#define XDIM 512
#define YDIM 512
#define NPIX (XDIM*YDIM)      // 262144
#define VNUM 150000
#define HID 64
#define CO 256
#define KEFF 2304             // 9 taps * 256 ch (single fp16 slot)
#define KROW 256              // per-pixel slots

// ---------------- scratch ----------------
__device__ __align__(256) float g_bev0[NPIX*HID];
__device__ __align__(256) float g_buf1[(size_t)NPIX*CO];
__device__ __align__(256) float g_buf2[(size_t)NPIX*CO];
__device__ __align__(256) __half g_a3a[(size_t)NPIX*KROW];
__device__ __align__(256) __half g_a3b[(size_t)NPIX*KROW];
__device__ __align__(256) float g_wt1[HID*CO];
__device__ __align__(256) __half g_bA[(size_t)CO*KEFF];
__device__ __align__(256) __half g_bB[(size_t)CO*KEFF];
__device__ __align__(256) float g_stats[4*CO];
__device__ __align__(256) float g_bn[4*CO];

__device__ __forceinline__ uint32_t smem_u32(const void* p) {
    uint32_t a;
    asm("{ .reg .u64 t; cvta.to.shared.u64 t, %1; cvt.u32.u64 %0, t; }" : "=r"(a) : "l"(p));
    return a;
}

#define LDSM_X4(r0,r1,r2,r3,addr) \
    asm volatile("ldmatrix.sync.aligned.m8n8.x4.shared.b16 {%0,%1,%2,%3}, [%4];" \
        : "=r"(r0),"=r"(r1),"=r"(r2),"=r"(r3) : "r"(addr))
#define MMA_F16(d, a, b) \
    asm volatile("mma.sync.aligned.m16n8k16.row.col.f32.f16.f16.f32 " \
        "{%0,%1,%2,%3},{%4,%5,%6,%7},{%8,%9},{%0,%1,%2,%3};" \
        : "+f"((d)[0]),"+f"((d)[1]),"+f"((d)[2]),"+f"((d)[3]) \
        : "r"((a)[0]),"r"((a)[1]),"r"((a)[2]),"r"((a)[3]),"r"((b)[0]),"r"((b)[1]))
#define CP_ASYNC(dst, src, sz) \
    asm volatile("cp.async.cg.shared.global [%0], [%1], 16, %2;" \
        :: "r"(dst), "l"(src), "r"(sz))
#define CP_COMMIT() asm volatile("cp.async.commit_group;")
#define CP_WAIT1()  asm volatile("cp.async.wait_group 1;")
#define CP_WAIT0()  asm volatile("cp.async.wait_group 0;")

// ---------------- zero bev + stats ----------------
__global__ void zero_kernel() {
    float4* p = (float4*)g_bev0;
    const int n4 = NPIX*HID/4;
    for (int i = blockIdx.x*blockDim.x + threadIdx.x; i < n4; i += gridDim.x*blockDim.x)
        p[i] = make_float4(0.f,0.f,0.f,0.f);
    if (blockIdx.x == 0)
        for (int i = threadIdx.x; i < 4*CO; i += blockDim.x) g_stats[i] = 0.f;
}

// ---------------- weight prep: conv1 transpose + fp16 B for convA/B ----------
__global__ void prep_weights(const float* __restrict__ c1w,
                             const float* __restrict__ cAw,
                             const float* __restrict__ cBw) {
    const int total1 = HID*CO;
    const int totalc = CO*CO*9;
    for (int i = blockIdx.x*blockDim.x + threadIdx.x; i < total1 + 2*totalc;
         i += gridDim.x*blockDim.x) {
        if (i < total1) {
            int o = i & 255, c = i >> 8;
            g_wt1[i] = c1w[o*HID + c];
        } else {
            int j = i - total1;
            const float* src = cAw; __half* dst = g_bA;
            if (j >= totalc) { j -= totalc; src = cBw; dst = g_bB; }
            int o = j / 2304, k = j % 2304;
            int c = k / 9, tap = k % 9;
            float w = src[(size_t)o*2304 + c*9 + tap];
            dst[(size_t)o*KEFF + tap*KROW + c] = __float2half_rn(w);
        }
    }
}

// ---------------- pillar MLP + pool + scatter ----------------
__global__ void __launch_bounds__(128) pillar_mlp(
    const float* __restrict__ pillars, const int* __restrict__ nump,
    const int* __restrict__ indices, const float* __restrict__ w1,
    const float* __restrict__ b1, const float* __restrict__ w2,
    const float* __restrict__ b2)
{
    __shared__ __align__(16) float w2q[64*64];
    __shared__ __align__(16) float h1s[2][32*64];
    __shared__ __align__(16) float pts[2][128];
    const int tid = threadIdx.x;
    const int g = tid >> 6, t = tid & 63;
    const int v = blockIdx.x*2 + g;

    for (int i = tid; i < 4096; i += 128) {
        int tt = i >> 6, j = i & 63;
        w2q[((j>>2)*64 + tt)*4 + (j&3)] = w2[i];
    }
    float4 w1r = *(const float4*)(w1 + t*4);
    float b1t = b1[t], b2t = b2[t];

    bool valid = false; int xy = 0;
    if (v < VNUM) {
        float mask = (nump[v] > 0) ? 1.f : 0.f;
        int xs = indices[2*v], ys = indices[2*v+1];
        if ((unsigned)xs < XDIM && (unsigned)ys < YDIM) { valid = true; xy = xs*YDIM + ys; }
        pts[g][t]      = pillars[(size_t)v*128 + t] * mask;
        pts[g][t + 64] = pillars[(size_t)v*128 + 64 + t] * mask;
    } else { pts[g][t] = 0.f; pts[g][t + 64] = 0.f; }
    __syncthreads();

    #pragma unroll
    for (int p = 0; p < 32; p++) {
        float4 xp = *(float4*)&pts[g][p*4];
        float h = fmaf(w1r.x, xp.x, fmaf(w1r.y, xp.y, fmaf(w1r.z, xp.z, fmaf(w1r.w, xp.w, b1t))));
        h1s[g][p*64 + t] = fmaxf(h, 0.f);
    }
    __syncthreads();

    float acc = 0.f;
    #pragma unroll
    for (int po = 0; po < 4; po++) {
        float s[8];
        #pragma unroll
        for (int pp = 0; pp < 8; pp++) s[pp] = b2t;
        #pragma unroll
        for (int jq = 0; jq < 16; jq++) {
            float4 w = *(float4*)&w2q[(jq*64 + t)*4];
            #pragma unroll
            for (int pp = 0; pp < 8; pp++) {
                float4 hh = *(float4*)&h1s[g][(po*8 + pp)*64 + jq*4];
                s[pp] = fmaf(w.x, hh.x, s[pp]); s[pp] = fmaf(w.y, hh.y, s[pp]);
                s[pp] = fmaf(w.z, hh.z, s[pp]); s[pp] = fmaf(w.w, hh.w, s[pp]);
            }
        }
        #pragma unroll
        for (int pp = 0; pp < 8; pp++) acc += fmaxf(s[pp], 0.f);
    }
    if (valid) g_bev0[(size_t)xy*HID + t] = acc * (1.f/32.f);
}

// ---------------- conv1 (1x1, 64->256) fp32 SIMT, emits fp16 A --------------
__global__ void __launch_bounds__(256) conv1_gemm(
    const float* __restrict__ in, const float* __restrict__ wt,
    const float* __restrict__ bias, __half* __restrict__ a3)
{
    __shared__ __align__(16) float As[16*68];
    __shared__ __align__(16) float Bs[16*64];
    const int tid = threadIdx.x;
    const int tx = tid & 15, ty = tid >> 4;
    const int pix0 = blockIdx.x * 64;
    const int o0 = blockIdx.y * 64;

    const int ai = tid >> 2;
    const int ak = (tid & 3) * 4;
    const int bj = tid & 63;
    const int bk0 = tid >> 6;

    float acc[4][4] = {};
    float4 av; float bv[4];
    #pragma unroll
    for (int k0 = 0; k0 < 64; k0 += 16) {
        av = *(const float4*)(in + (size_t)(pix0 + ai)*HID + k0 + ak);
        #pragma unroll
        for (int m = 0; m < 4; m++) bv[m] = wt[(size_t)(k0 + bk0 + m*4)*CO + o0 + bj];
        As[(ak+0)*68 + ai] = av.x; As[(ak+1)*68 + ai] = av.y;
        As[(ak+2)*68 + ai] = av.z; As[(ak+3)*68 + ai] = av.w;
        #pragma unroll
        for (int m = 0; m < 4; m++) Bs[(bk0 + m*4)*64 + bj] = bv[m];
        __syncthreads();
        #pragma unroll
        for (int kk = 0; kk < 16; kk++) {
            float4 a4 = *(float4*)&As[kk*68 + ty*4];
            float4 b4 = *(float4*)&Bs[kk*64 + tx*4];
            float aa[4] = {a4.x,a4.y,a4.z,a4.w}, bb[4] = {b4.x,b4.y,b4.z,b4.w};
            #pragma unroll
            for (int r = 0; r < 4; r++)
                #pragma unroll
                for (int c = 0; c < 4; c++) acc[r][c] = fmaf(aa[r], bb[c], acc[r][c]);
        }
        __syncthreads();
    }
    float4 bvz = *(const float4*)(bias + o0 + tx*4);
    float bbias[4] = {bvz.x,bvz.y,bvz.z,bvz.w};
    #pragma unroll
    for (int r = 0; r < 4; r++) {
        int pix = pix0 + ty*4 + r;
        __half h[4];
        #pragma unroll
        for (int c = 0; c < 4; c++) h[c] = __float2half_rn(acc[r][c] + bbias[c]);
        uint2 pk = make_uint2(
            ((uint32_t)__half_as_ushort(h[0])) | ((uint32_t)__half_as_ushort(h[1]) << 16),
            ((uint32_t)__half_as_ushort(h[2])) | ((uint32_t)__half_as_ushort(h[3]) << 16));
        *(uint2*)(a3 + (size_t)pix*KROW + o0 + tx*4) = pk;
    }
}

// ---------------- mma.sync 3x3 conv: 128 pix x 128 oc tile, K=2304 ----------
// 8 warps (2M x 4N), warp tile 64x32, 36 chunks of 64 K, cp.async dbl-buffer
__global__ void __launch_bounds__(256, 2) conv_mma(
    const __half* __restrict__ a3w, const __half* __restrict__ b3w,
    const float* __restrict__ bias, float* __restrict__ out,
    float* __restrict__ sumb, float* __restrict__ sqb)
{
    extern __shared__ char sm[];
    const char* a3 = (const char*)a3w;
    const char* b3 = (const char*)b3w;
    const int tid = threadIdx.x, wid = tid >> 5, lane = tid & 31;
    const int wm = wid >> 2, wn = wid & 3;
    const uint32_t sb = smem_u32(sm);
    float* sbias = (float*)(sm + 65536);

    const int xr = blockIdx.x >> 2;               // x-row 0..511
    const int y0 = (blockIdx.x & 3) * 128;        // y base
    const int p0 = xr*512 + y0;
    const int o0 = blockIdx.y * 128;

    sbias[tid] = bias[tid];

    // per-lane ldmatrix offsets (no-trans; rows = m for A, n for B; k along row)
    const int a_row = wm*64 + (lane & 15);
    const int a_kb  = (lane >> 4) * 16;
    const int b_row = wn*32 + ((lane & 16) >> 1) + (lane & 7);
    const int b_kb  = (lane & 8) ? 16 : 0;

    // cp.async thread mapping
    const int l_row = tid >> 3;        // 0..31, +32 per i
    const int l_j   = (tid & 7) * 16;  // byte col

    float acc[4][4][4];
    #pragma unroll
    for (int i = 0; i < 4; i++)
        #pragma unroll
        for (int j = 0; j < 4; j++)
            #pragma unroll
            for (int k = 0; k < 4; k++) acc[i][j][k] = 0.f;

    auto load_chunk = [&](int c, int buf) {
        const int tap = c >> 2, kc = c & 3;
        const int dx = tap/3 - 1, dyy = tap - (tap/3)*3 - 1;
        const int xx = xr + dx;
        const bool xok = (unsigned)xx < XDIM;
        const uint32_t abase = sb + buf*16384u;
        const uint32_t bbase = sb + 32768u + buf*16384u;
        #pragma unroll
        for (int i = 0; i < 4; i++) {
            int row = l_row + i*32;
            int yy = y0 + row + dyy;
            bool ok = xok && ((unsigned)yy < YDIM);
            const char* src = ok ? (a3 + ((size_t)(xx*512 + yy))*512 + kc*128 + l_j)
                                 : a3;
            uint32_t off = row*128 + l_j; off ^= (off >> 3) & 0x70;
            CP_ASYNC(abase + off, src, ok ? 16 : 0);
        }
        #pragma unroll
        for (int i = 0; i < 4; i++) {
            int row = l_row + i*32;
            const char* src = b3 + (size_t)(o0 + row)*4608 + tap*512 + kc*128 + l_j;
            uint32_t off = row*128 + l_j; off ^= (off >> 3) & 0x70;
            CP_ASYNC(bbase + off, src, 16);
        }
    };

    load_chunk(0, 0);
    CP_COMMIT();

    for (int c = 0; c < 36; c++) {
        const int buf = c & 1;
        if (c + 1 < 36) { load_chunk(c + 1, buf ^ 1); CP_COMMIT(); CP_WAIT1(); }
        else            { CP_WAIT0(); }
        __syncthreads();

        const uint32_t sa  = sb + buf*16384u;
        const uint32_t sbm = sb + 32768u + buf*16384u;
        #pragma unroll
        for (int ks = 0; ks < 4; ks++) {
            uint32_t af[4][4], bf[4][2];
            #pragma unroll
            for (int mt = 0; mt < 4; mt++) {
                uint32_t off = (a_row + mt*16)*128 + a_kb + ks*32;
                off ^= (off >> 3) & 0x70;
                LDSM_X4(af[mt][0], af[mt][1], af[mt][2], af[mt][3], sa + off);
            }
            #pragma unroll
            for (int pr = 0; pr < 2; pr++) {
                uint32_t off = (b_row + pr*16)*128 + b_kb + ks*32;
                off ^= (off >> 3) & 0x70;
                LDSM_X4(bf[pr*2][0], bf[pr*2][1], bf[pr*2+1][0], bf[pr*2+1][1], sbm + off);
            }
            #pragma unroll
            for (int mt = 0; mt < 4; mt++)
                #pragma unroll
                for (int nt = 0; nt < 4; nt++)
                    MMA_F16(acc[mt][nt], af[mt], bf[nt]);
        }
        __syncthreads();
    }

    // epilogue: bias add, HWC store, BN stats
    #pragma unroll
    for (int nt = 0; nt < 4; nt++) {
        const int col = o0 + wn*32 + nt*8 + (lane & 3)*2;
        const float bs0 = sbias[col];
        const float bs1 = sbias[col + 1];
        float s0 = 0.f, q0 = 0.f, s1 = 0.f, q1 = 0.f;
        #pragma unroll
        for (int mt = 0; mt < 4; mt++) {
            const int prow = p0 + wm*64 + mt*16 + (lane >> 2);
            float v00 = acc[mt][nt][0] + bs0;
            float v01 = acc[mt][nt][1] + bs1;
            float v10 = acc[mt][nt][2] + bs0;
            float v11 = acc[mt][nt][3] + bs1;
            *(float2*)(out + (size_t)prow*CO + col)     = make_float2(v00, v01);
            *(float2*)(out + (size_t)(prow+8)*CO + col) = make_float2(v10, v11);
            s0 += v00 + v10; q0 += v00*v00 + v10*v10;
            s1 += v01 + v11; q1 += v01*v01 + v11*v11;
        }
        #pragma unroll
        for (int o = 4; o < 32; o <<= 1) {
            s0 += __shfl_xor_sync(0xffffffffu, s0, o);
            q0 += __shfl_xor_sync(0xffffffffu, q0, o);
            s1 += __shfl_xor_sync(0xffffffffu, s1, o);
            q1 += __shfl_xor_sync(0xffffffffu, q1, o);
        }
        if (lane < 4) {
            atomicAdd(sumb + col, s0); atomicAdd(sqb + col, q0);
            atomicAdd(sumb + col + 1, s1); atomicAdd(sqb + col + 1, q1);
        }
    }
}

// ---------------- BN finalize ----------------
__global__ void bn_finalize(const float* __restrict__ gamma,
                            const float* __restrict__ beta, int which) {
    int c = threadIdx.x;
    const float inv_n = 1.f / (float)NPIX;
    float mean = g_stats[which*512 + c] * inv_n;
    float var  = g_stats[which*512 + 256 + c] * inv_n - mean*mean;
    float sc = gamma[c] * rsqrtf(var + 1e-5f);
    g_bn[which*512 + c] = sc;
    g_bn[which*512 + 256 + c] = fmaf(-mean, sc, beta[c]);
}

// ---------------- BN-A apply + relu + fp16 convert ----------------
__global__ void bn_convert(const float* __restrict__ in, __half* __restrict__ a3) {
    __shared__ float sc[256], sh[256];
    if (threadIdx.x < 256) {
        sc[threadIdx.x] = g_bn[threadIdx.x];
        sh[threadIdx.x] = g_bn[256 + threadIdx.x];
    }
    __syncthreads();
    const float4* in4 = (const float4*)in;
    const int total4 = NPIX * 64;
    for (int i = blockIdx.x*blockDim.x + threadIdx.x; i < total4; i += gridDim.x*blockDim.x) {
        float4 v = in4[i];
        int c = (i & 63) * 4;
        size_t pix = (size_t)(i >> 6);
        float f[4] = {v.x, v.y, v.z, v.w};
        __half h[4];
        #pragma unroll
        for (int cc = 0; cc < 4; cc++)
            h[cc] = __float2half_rn(fmaxf(fmaf(f[cc], sc[c+cc], sh[c+cc]), 0.f));
        uint2 pk = make_uint2(
            ((uint32_t)__half_as_ushort(h[0])) | ((uint32_t)__half_as_ushort(h[1]) << 16),
            ((uint32_t)__half_as_ushort(h[2])) | ((uint32_t)__half_as_ushort(h[3]) << 16));
        *(uint2*)(a3 + pix*KROW + c) = pk;
    }
}

// ---------------- BN-B apply + relu + HWC->NCHW ----------------
__global__ void __launch_bounds__(256) bn_apply_nchw(const float* __restrict__ in,
                                                     float* __restrict__ out) {
    __shared__ float s[32*257];
    const int tid = threadIdx.x;
    const float sc = g_bn[512 + tid];
    const float sh = g_bn[768 + tid];
    const int xy0 = blockIdx.x * 32;
    #pragma unroll
    for (int m = 0; m < 32; m++) {
        float v = in[(size_t)(xy0 + m)*CO + tid];
        s[m*257 + tid] = fmaxf(fmaf(v, sc, sh), 0.f);
    }
    __syncthreads();
    #pragma unroll
    for (int m = 0; m < 32; m++) {
        int o = m*8 + (tid >> 5);
        int xyl = tid & 31;
        out[(size_t)o*NPIX + xy0 + xyl] = s[xyl*257 + o];
    }
}

// ---------------- launch ----------------
extern "C" void kernel_launch(void* const* d_in, const int* in_sizes, int n_in,
                              void* d_out, int out_size) {
    const float* pillars = (const float*)d_in[0];
    const int*   nump    = (const int*)d_in[1];
    const int*   indices = (const int*)d_in[2];
    const float* w1   = (const float*)d_in[3];
    const float* b1   = (const float*)d_in[4];
    const float* w2   = (const float*)d_in[5];
    const float* b2   = (const float*)d_in[6];
    const float* c1w  = (const float*)d_in[7];
    const float* c1b  = (const float*)d_in[8];
    const float* cAw  = (const float*)d_in[9];
    const float* cAb  = (const float*)d_in[10];
    const float* bnAg = (const float*)d_in[11];
    const float* bnAb = (const float*)d_in[12];
    const float* cBw  = (const float*)d_in[13];
    const float* cBb  = (const float*)d_in[14];
    const float* bnBg = (const float*)d_in[15];
    const float* bnBb = (const float*)d_in[16];
    float* out = (float*)d_out;

    float *p_bev0, *p_buf1, *p_buf2, *p_wt1, *p_stats;
    __half *p_a3a, *p_a3b, *p_bA, *p_bB;
    cudaGetSymbolAddress((void**)&p_bev0,  g_bev0);
    cudaGetSymbolAddress((void**)&p_buf1,  g_buf1);
    cudaGetSymbolAddress((void**)&p_buf2,  g_buf2);
    cudaGetSymbolAddress((void**)&p_wt1,   g_wt1);
    cudaGetSymbolAddress((void**)&p_stats, g_stats);
    cudaGetSymbolAddress((void**)&p_a3a,   g_a3a);
    cudaGetSymbolAddress((void**)&p_a3b,   g_a3b);
    cudaGetSymbolAddress((void**)&p_bA,    g_bA);
    cudaGetSymbolAddress((void**)&p_bB,    g_bB);

    static bool attr_done = false;
    if (!attr_done) {
        cudaFuncSetAttribute(conv_mma, cudaFuncAttributeMaxDynamicSharedMemorySize, 66560);
        attr_done = true;
    }

    zero_kernel<<<2048, 256>>>();
    prep_weights<<<1200, 256>>>(c1w, cAw, cBw);
    pillar_mlp<<<(VNUM + 1)/2, 128>>>(pillars, nump, indices, w1, b1, w2, b2);

    dim3 c1grid(NPIX/64, 4);
    conv1_gemm<<<c1grid, 256>>>(p_bev0, p_wt1, c1b, p_a3a);

    dim3 cgrid(2048, 2);
    conv_mma<<<cgrid, 256, 66560>>>(p_a3a, p_bA, cAb, p_buf1, p_stats, p_stats + 256);
    bn_finalize<<<1, 256>>>(bnAg, bnAb, 0);

    bn_convert<<<4096, 256>>>(p_buf1, p_a3b);

    conv_mma<<<cgrid, 256, 66560>>>(p_a3b, p_bB, cBb, p_buf2, p_stats + 512, p_stats + 768);
    bn_finalize<<<1, 256>>>(bnBg, bnBb, 1);

    bn_apply_nchw<<<NPIX/32, 256>>>(p_buf2, out);
}